// round 5
// baseline (speedup 1.0000x reference)
#include <cuda_runtime.h>
#include <cuda_bf16.h>

#define N_NODES 50000
#define N_EDGES 800000
#define DIN     128
#define D1      256
#define NH      4
#define NC      520   // 256 (xs) + 256 (lin) + 4 (a_s) + 4 (a_d)

// ---------------- static scratch (no allocations allowed) ----------------
__device__ __align__(128) float d_Y[(size_t)N_NODES * NC];   // fused GEMM out
__device__ __align__(128) float d_h[(size_t)N_NODES * D1];   // layer-1 hidden
__device__ __align__(128) float d_alpha[(size_t)N_EDGES * NH]; // raw e scores (scratch)
__device__ __align__(128) float d_Wcat[256 * NC];            // packed weights (max K=256)
__device__ int d_srcs[N_EDGES];
__device__ int d_rowptr[N_NODES + 1];
__device__ int d_cursor[N_NODES];
__device__ int d_deg[N_NODES];
__device__ int d_csum[128];

// ---------------- CSR build ----------------
__global__ void zero_deg_kernel() {
    int i = blockIdx.x * blockDim.x + threadIdx.x;
    if (i < N_NODES) d_deg[i] = 0;
}

__global__ void count_deg_kernel(const int* __restrict__ dst) {
    int e = blockIdx.x * blockDim.x + threadIdx.x;
    if (e < N_EDGES) atomicAdd(&d_deg[dst[e]], 1);
}

__global__ void scan1_kernel() {  // per-chunk (512) sums
    __shared__ int s[512];
    int i = blockIdx.x * 512 + threadIdx.x;
    s[threadIdx.x] = (i < N_NODES) ? d_deg[i] : 0;
    __syncthreads();
    for (int off = 256; off; off >>= 1) {
        if (threadIdx.x < off) s[threadIdx.x] += s[threadIdx.x + off];
        __syncthreads();
    }
    if (threadIdx.x == 0) d_csum[blockIdx.x] = s[0];
}

__global__ void scan2_kernel(int nb) {  // serial exclusive scan of chunk sums (tiny)
    if (threadIdx.x == 0 && blockIdx.x == 0) {
        int acc = 0;
        for (int i = 0; i < nb; i++) { int t = d_csum[i]; d_csum[i] = acc; acc += t; }
    }
}

__global__ void scan3_kernel() {  // intra-chunk scan -> rowptr, cursor
    __shared__ int s[512];
    int i = blockIdx.x * 512 + threadIdx.x;
    int v = (i < N_NODES) ? d_deg[i] : 0;
    s[threadIdx.x] = v;
    __syncthreads();
    for (int off = 1; off < 512; off <<= 1) {
        int t = (threadIdx.x >= off) ? s[threadIdx.x - off] : 0;
        __syncthreads();
        s[threadIdx.x] += t;
        __syncthreads();
    }
    if (i < N_NODES) {
        int excl = d_csum[blockIdx.x] + s[threadIdx.x] - v;
        d_rowptr[i] = excl;
        d_cursor[i] = excl;
        if (i == N_NODES - 1) d_rowptr[N_NODES] = excl + v;
    }
}

__global__ void fill_csr_kernel(const int* __restrict__ src, const int* __restrict__ dst) {
    int e = blockIdx.x * blockDim.x + threadIdx.x;
    if (e >= N_EDGES) return;
    int pos = atomicAdd(&d_cursor[dst[e]], 1);
    d_srcs[pos] = src[e];
}

// ---------------- weight packing: Wcat = [Wsrc | Wlin | Wsrc.atts | Wdst.attd] ----------------
__global__ void pack_kernel(const float* __restrict__ Wsrc, const float* __restrict__ Wlin,
                            const float* __restrict__ Wdst, const float* __restrict__ atts,
                            const float* __restrict__ attd) {
    int k = blockIdx.x;   // one block per K-row
    int t = threadIdx.x;  // 256 threads
    d_Wcat[k * NC + t]       = Wsrc[k * D1 + t];
    d_Wcat[k * NC + 256 + t] = Wlin[k * D1 + t];
    if (t < 8) {
        int h = t & 3;
        const float* W  = (t < 4) ? Wsrc : Wdst;
        const float* at = (t < 4) ? atts : attd;
        float s = 0.f;
        #pragma unroll 8
        for (int c = 0; c < 64; c++) s += W[k * D1 + h * 64 + c] * at[h * 64 + c];
        d_Wcat[k * NC + 512 + t] = s;  // cols 512..515 = a_s weights, 516..519 = a_d weights
    }
}

// -------- fused GEMM: Y[M, NC] = X[M,K] @ Wcat[K, NC] (+blin on lin cols) --------
// 256x64 tile / block, 256 threads, 8x8 microtile, BK=16, double-buffered smem.
__global__ void __launch_bounds__(256, 2) gemm_kernel(
        const float* __restrict__ Xin, const float* __restrict__ blin,
        int M, int K, int use_h) {
    __shared__ float As[2][16][256];
    __shared__ float Bs[2][16][64];
    const float* __restrict__ X = use_h ? d_h : Xin;
    const int t = threadIdx.x;
    const int bn = blockIdx.x * 64, bm = blockIdx.y * 256;
    const int ty = t >> 3;            // 0..31, 8 rows each
    const int tx = t & 7;             // 0..7,  8 cols each
    const int brow = t >> 4;          // B-load row 0..15
    const int bnq  = (t & 15) * 4;    // B-load col quad

    float acc[8][8] = {};
    float4 pa[4], pb;

    // ---- prologue: tile 0 -> regs ----
    #pragma unroll
    for (int l = 0; l < 4; l++) {
        int f = t + l * 256;
        int arow = f >> 2, akq = (f & 3) * 4;
        pa[l] = make_float4(0.f, 0.f, 0.f, 0.f);
        if (bm + arow < M) pa[l] = *(const float4*)&X[(size_t)(bm + arow) * K + akq];
    }
    {
        int n = bn + bnq;
        pb = make_float4(0.f, 0.f, 0.f, 0.f);
        if (n + 4 <= NC) pb = *(const float4*)&d_Wcat[(size_t)brow * NC + n];
    }
    // ---- regs -> smem buf 0 ----
    #pragma unroll
    for (int l = 0; l < 4; l++) {
        int f = t + l * 256;
        int arow = f >> 2, akq = (f & 3) * 4;
        As[0][akq + 0][arow] = pa[l].x;
        As[0][akq + 1][arow] = pa[l].y;
        As[0][akq + 2][arow] = pa[l].z;
        As[0][akq + 3][arow] = pa[l].w;
    }
    *(float4*)&Bs[0][brow][bnq] = pb;
    __syncthreads();

    int buf = 0;
    for (int k0 = 0; k0 < K; k0 += 16) {
        const bool has_next = (k0 + 16) < K;
        if (has_next) {
            #pragma unroll
            for (int l = 0; l < 4; l++) {
                int f = t + l * 256;
                int arow = f >> 2, akq = (f & 3) * 4;
                pa[l] = make_float4(0.f, 0.f, 0.f, 0.f);
                if (bm + arow < M)
                    pa[l] = *(const float4*)&X[(size_t)(bm + arow) * K + k0 + 16 + akq];
            }
            int n = bn + bnq;
            pb = make_float4(0.f, 0.f, 0.f, 0.f);
            if (n + 4 <= NC) pb = *(const float4*)&d_Wcat[(size_t)(k0 + 16 + brow) * NC + n];
        }
        const float* Ab = &As[buf][0][0];
        const float* Bb = &Bs[buf][0][0];
        #pragma unroll
        for (int kk = 0; kk < 16; kk++) {
            float4 a0 = *(const float4*)&Ab[kk * 256 + ty * 8];
            float4 a1 = *(const float4*)&Ab[kk * 256 + ty * 8 + 4];
            float4 b0 = *(const float4*)&Bb[kk * 64 + tx * 8];
            float4 b1 = *(const float4*)&Bb[kk * 64 + tx * 8 + 4];
            float a[8] = {a0.x, a0.y, a0.z, a0.w, a1.x, a1.y, a1.z, a1.w};
            float b[8] = {b0.x, b0.y, b0.z, b0.w, b1.x, b1.y, b1.z, b1.w};
            #pragma unroll
            for (int i = 0; i < 8; i++)
                #pragma unroll
                for (int j = 0; j < 8; j++) acc[i][j] += a[i] * b[j];
        }
        if (has_next) {
            int nb2 = buf ^ 1;
            #pragma unroll
            for (int l = 0; l < 4; l++) {
                int f = t + l * 256;
                int arow = f >> 2, akq = (f & 3) * 4;
                As[nb2][akq + 0][arow] = pa[l].x;
                As[nb2][akq + 1][arow] = pa[l].y;
                As[nb2][akq + 2][arow] = pa[l].z;
                As[nb2][akq + 3][arow] = pa[l].w;
            }
            *(float4*)&Bs[nb2][brow][bnq] = pb;
            __syncthreads();
            buf = nb2;
        }
    }

    // ---- epilogue: acc -> d_Y (add blin on lin cols), float4 stores ----
    #pragma unroll
    for (int i = 0; i < 8; i++) {
        int m = bm + ty * 8 + i;
        if (m >= M) continue;
        #pragma unroll
        for (int jq = 0; jq < 8; jq += 4) {
            int n = bn + tx * 8 + jq;
            if (n + 4 > NC) continue;
            float4 v = make_float4(acc[i][jq], acc[i][jq + 1], acc[i][jq + 2], acc[i][jq + 3]);
            if (n >= 256 && n < 512) {
                v.x += blin[n - 256];
                v.y += blin[n - 255];
                v.z += blin[n - 254];
                v.w += blin[n - 253];
            }
            *(float4*)&d_Y[(size_t)m * NC + n] = v;
        }
    }
}

// -------- fused softmax + aggregation: one warp per node --------
// Pass A: gather scores once, write raw e to d_alpha, warp-max.
// Pass B: stream e, warp-sum exp(e-m).
// Pass C: stream e + gather xs rows, alpha inline, FMA. Lane owns channels lane+32j.
// do_ln=1: fused LayerNorm+ReLU epilogue (layer 1 -> d_h). do_ln=0: plain (layer 2 -> out).
__global__ void aggr_kernel(const float* __restrict__ bias,
                            const float* __restrict__ gamma, const float* __restrict__ beta,
                            float* __restrict__ out_param, int do_ln) {
    int wid  = (blockIdx.x * blockDim.x + threadIdx.x) >> 5;
    int lane = threadIdx.x & 31;
    if (wid >= N_NODES) return;
    int node = wid;
    int row0 = d_rowptr[node];
    int deg  = d_rowptr[node + 1] - row0;

    float m0 = -1e30f, m1 = -1e30f, m2 = -1e30f, m3 = -1e30f;
    if (deg > 0) {
        const float4 adv = *(const float4*)&d_Y[(size_t)node * NC + 516];
        // ---- pass A: gather a_s, compute e, store, track max ----
        for (int i = lane; i < deg; i += 32) {
            int s = d_srcs[row0 + i];
            const float4 as4 = __ldg((const float4*)&d_Y[(size_t)s * NC + 512]);
            float e0 = as4.x + adv.x; e0 = e0 > 0.f ? e0 : 0.2f * e0;
            float e1 = as4.y + adv.y; e1 = e1 > 0.f ? e1 : 0.2f * e1;
            float e2 = as4.z + adv.z; e2 = e2 > 0.f ? e2 : 0.2f * e2;
            float e3 = as4.w + adv.w; e3 = e3 > 0.f ? e3 : 0.2f * e3;
            *(float4*)&d_alpha[(size_t)(row0 + i) * 4] = make_float4(e0, e1, e2, e3);
            m0 = fmaxf(m0, e0); m1 = fmaxf(m1, e1); m2 = fmaxf(m2, e2); m3 = fmaxf(m3, e3);
        }
        #pragma unroll
        for (int off = 16; off; off >>= 1) {
            m0 = fmaxf(m0, __shfl_xor_sync(0xffffffffu, m0, off));
            m1 = fmaxf(m1, __shfl_xor_sync(0xffffffffu, m1, off));
            m2 = fmaxf(m2, __shfl_xor_sync(0xffffffffu, m2, off));
            m3 = fmaxf(m3, __shfl_xor_sync(0xffffffffu, m3, off));
        }
    }

    // ---- pass B: sum exp(e - m) ----
    float s0 = 0.f, s1 = 0.f, s2 = 0.f, s3 = 0.f;
    for (int i = lane; i < deg; i += 32) {
        float4 e = *(const float4*)&d_alpha[(size_t)(row0 + i) * 4];
        s0 += __expf(e.x - m0); s1 += __expf(e.y - m1);
        s2 += __expf(e.z - m2); s3 += __expf(e.w - m3);
    }
    #pragma unroll
    for (int off = 16; off; off >>= 1) {
        s0 += __shfl_xor_sync(0xffffffffu, s0, off);
        s1 += __shfl_xor_sync(0xffffffffu, s1, off);
        s2 += __shfl_xor_sync(0xffffffffu, s2, off);
        s3 += __shfl_xor_sync(0xffffffffu, s3, off);
    }
    // per-head scale factors folded with the base: alpha = exp(e-m) * r
    float r[4] = {1.f / (s0 + 1e-16f), 1.f / (s1 + 1e-16f),
                  1.f / (s2 + 1e-16f), 1.f / (s3 + 1e-16f)};
    float mh[4] = {m0, m1, m2, m3};

    // ---- pass C: gather rows, weighted accumulate ----
    float acc[8] = {};
    int i = 0;
    for (; i + 2 <= deg; i += 2) {
        int p = row0 + i;
        int sA = d_srcs[p], sB = d_srcs[p + 1];
        float4 eA = *(const float4*)&d_alpha[(size_t)p * 4];
        float4 eB = *(const float4*)&d_alpha[(size_t)(p + 1) * 4];
        const float* xA = &d_Y[(size_t)sA * NC + lane];
        const float* xB = &d_Y[(size_t)sB * NC + lane];
        float vA[8], vB[8];
        #pragma unroll
        for (int j = 0; j < 8; j++) vA[j] = xA[j * 32];
        #pragma unroll
        for (int j = 0; j < 8; j++) vB[j] = xB[j * 32];
        float aA[4] = {__expf(eA.x - mh[0]) * r[0], __expf(eA.y - mh[1]) * r[1],
                       __expf(eA.z - mh[2]) * r[2], __expf(eA.w - mh[3]) * r[3]};
        float aB[4] = {__expf(eB.x - mh[0]) * r[0], __expf(eB.y - mh[1]) * r[1],
                       __expf(eB.z - mh[2]) * r[2], __expf(eB.w - mh[3]) * r[3]};
        #pragma unroll
        for (int j = 0; j < 8; j++) acc[j] += aA[j >> 1] * vA[j] + aB[j >> 1] * vB[j];
    }
    for (; i < deg; i++) {
        int p = row0 + i;
        int s = d_srcs[p];
        float4 e = *(const float4*)&d_alpha[(size_t)p * 4];
        const float* xr = &d_Y[(size_t)s * NC + lane];
        float a[4] = {__expf(e.x - mh[0]) * r[0], __expf(e.y - mh[1]) * r[1],
                      __expf(e.z - mh[2]) * r[2], __expf(e.w - mh[3]) * r[3]};
        #pragma unroll
        for (int j = 0; j < 8; j++) acc[j] += a[j >> 1] * xr[j * 32];
    }

    // add skip (lin cols) + bias
    const float* yrow = &d_Y[(size_t)node * NC + 256 + lane];
    #pragma unroll
    for (int j = 0; j < 8; j++) acc[j] += yrow[j * 32] + bias[lane + j * 32];

    if (do_ln) {
        float sum = 0.f;
        #pragma unroll
        for (int j = 0; j < 8; j++) sum += acc[j];
        #pragma unroll
        for (int off = 16; off; off >>= 1) sum += __shfl_xor_sync(0xffffffffu, sum, off);
        float mu = sum * (1.f / 256.f);
        float vs = 0.f;
        #pragma unroll
        for (int j = 0; j < 8; j++) vs += (acc[j] - mu) * (acc[j] - mu);
        #pragma unroll
        for (int off = 16; off; off >>= 1) vs += __shfl_xor_sync(0xffffffffu, vs, off);
        float rstd = rsqrtf(vs * (1.f / 256.f) + 1e-5f);
        #pragma unroll
        for (int j = 0; j < 8; j++) {
            int c = lane + j * 32;
            float y = (acc[j] - mu) * rstd * gamma[c] + beta[c];
            d_h[(size_t)node * D1 + c] = y > 0.f ? y : 0.f;
        }
    } else {
        #pragma unroll
        for (int j = 0; j < 8; j++)
            out_param[(size_t)node * D1 + lane + j * 32] = acc[j];
    }
}

// ---------------- launch ----------------
extern "C" void kernel_launch(void* const* d_in, const int* in_sizes, int n_in,
                              void* d_out, int out_size) {
    const float* x      = (const float*)d_in[0];
    const int*   ei     = (const int*)d_in[1];
    const int*   src    = ei;
    const int*   dst    = ei + N_EDGES;
    const float* Wsrc1  = (const float*)d_in[2];
    const float* Wdst1  = (const float*)d_in[3];
    const float* atts1  = (const float*)d_in[4];
    const float* attd1  = (const float*)d_in[5];
    const float* b1     = (const float*)d_in[6];
    const float* Wlin1  = (const float*)d_in[7];
    const float* blin1  = (const float*)d_in[8];
    const float* gamma  = (const float*)d_in[9];
    const float* beta   = (const float*)d_in[10];
    const float* Wsrc2  = (const float*)d_in[11];
    const float* Wdst2  = (const float*)d_in[12];
    const float* atts2  = (const float*)d_in[13];
    const float* attd2  = (const float*)d_in[14];
    const float* b2     = (const float*)d_in[15];
    const float* Wlin2  = (const float*)d_in[16];
    const float* blin2  = (const float*)d_in[17];
    float* out = (float*)d_out;

    const int scan_blocks = (N_NODES + 511) / 512;  // 98

    // CSR build (per-launch, idempotent)
    zero_deg_kernel<<<(N_NODES + 255) / 256, 256>>>();
    count_deg_kernel<<<(N_EDGES + 255) / 256, 256>>>(dst);
    scan1_kernel<<<scan_blocks, 512>>>();
    scan2_kernel<<<1, 32>>>(scan_blocks);
    scan3_kernel<<<scan_blocks, 512>>>();
    fill_csr_kernel<<<(N_EDGES + 255) / 256, 256>>>(src, dst);

    dim3 ggrid((NC + 63) / 64, (N_NODES + 255) / 256);  // (9, 196)

    // ---- layer 1 ----
    pack_kernel<<<DIN, 256>>>(Wsrc1, Wlin1, Wdst1, atts1, attd1);
    gemm_kernel<<<ggrid, 256>>>(x, blin1, N_NODES, DIN, /*use_h=*/0);
    aggr_kernel<<<(N_NODES + 7) / 8, 256>>>(b1, gamma, beta, nullptr, /*do_ln=*/1);

    // ---- layer 2 ----
    pack_kernel<<<D1, 256>>>(Wsrc2, Wlin2, Wdst2, atts2, attd2);
    gemm_kernel<<<ggrid, 256>>>(x, blin2, N_NODES, D1, /*use_h=*/1);
    aggr_kernel<<<(N_NODES + 7) / 8, 256>>>(b2, nullptr, nullptr, out, /*do_ln=*/0);
}

// round 7
// speedup vs baseline: 1.4937x; 1.4937x over previous
#include <cuda_runtime.h>
#include <cuda_bf16.h>
#include <cstdint>

#define N_NODES 50000
#define N_EDGES 800000
#define DIN     128
#define D1      256
#define NH      4
#define KMAX    256
#define NCP     576   // padded GEMM N: [0,256)=xs [256,260)=a_s [260,264)=a_d [264,320)=0 [320,576)=lin
#define N_XS    320
#define N_LIN   256

// ---------------- static scratch (no allocations allowed) ----------------
__device__ __align__(128) float d_Xs[(size_t)N_NODES * N_XS];    // xs + scores (gather buffer)
__device__ __align__(128) float d_Lin[(size_t)N_NODES * N_LIN];  // lin skip
__device__ __align__(128) float d_alpha[(size_t)N_EDGES * NH];   // raw e scores (scratch)
__device__ __align__(128) __nv_bfloat16 d_Xh[(size_t)N_NODES * KMAX];  // GEMM input hi
__device__ __align__(128) __nv_bfloat16 d_Xl[(size_t)N_NODES * KMAX];  // GEMM input lo
__device__ __align__(128) __nv_bfloat16 d_Wth[NCP * KMAX];       // W^T hi  [n][k]
__device__ __align__(128) __nv_bfloat16 d_Wtl[NCP * KMAX];       // W^T lo
__device__ int d_srcs[N_EDGES];
__device__ int d_rowptr[N_NODES + 1];
__device__ int d_cursor[N_NODES];
__device__ int d_deg[N_NODES];
__device__ int d_csum[128];

__device__ __forceinline__ void split_bf16(float x, __nv_bfloat16& h, __nv_bfloat16& l) {
    h = __float2bfloat16(x);
    l = __float2bfloat16(x - __bfloat162float(h));
}

// ---------------- CSR build ----------------
__global__ void zero_deg_kernel() {
    int i = blockIdx.x * blockDim.x + threadIdx.x;
    if (i < N_NODES) d_deg[i] = 0;
}

__global__ void count_deg_kernel(const int* __restrict__ dst) {
    int e = blockIdx.x * blockDim.x + threadIdx.x;
    if (e < N_EDGES) atomicAdd(&d_deg[dst[e]], 1);
}

__global__ void scan1_kernel() {
    __shared__ int s[512];
    int i = blockIdx.x * 512 + threadIdx.x;
    s[threadIdx.x] = (i < N_NODES) ? d_deg[i] : 0;
    __syncthreads();
    for (int off = 256; off; off >>= 1) {
        if (threadIdx.x < off) s[threadIdx.x] += s[threadIdx.x + off];
        __syncthreads();
    }
    if (threadIdx.x == 0) d_csum[blockIdx.x] = s[0];
}

__global__ void scan2_kernel(int nb) {
    if (threadIdx.x == 0 && blockIdx.x == 0) {
        int acc = 0;
        for (int i = 0; i < nb; i++) { int t = d_csum[i]; d_csum[i] = acc; acc += t; }
    }
}

__global__ void scan3_kernel() {
    __shared__ int s[512];
    int i = blockIdx.x * 512 + threadIdx.x;
    int v = (i < N_NODES) ? d_deg[i] : 0;
    s[threadIdx.x] = v;
    __syncthreads();
    for (int off = 1; off < 512; off <<= 1) {
        int t = (threadIdx.x >= off) ? s[threadIdx.x - off] : 0;
        __syncthreads();
        s[threadIdx.x] += t;
        __syncthreads();
    }
    if (i < N_NODES) {
        int excl = d_csum[blockIdx.x] + s[threadIdx.x] - v;
        d_rowptr[i] = excl;
        d_cursor[i] = excl;
        if (i == N_NODES - 1) d_rowptr[N_NODES] = excl + v;
    }
}

__global__ void fill_csr_kernel(const int* __restrict__ src, const int* __restrict__ dst) {
    int e = blockIdx.x * blockDim.x + threadIdx.x;
    if (e >= N_EDGES) return;
    int pos = atomicAdd(&d_cursor[dst[e]], 1);
    d_srcs[pos] = src[e];
}

// ---------------- input conversion: fp32 -> bf16 hi/lo (layer 1 only) ----------------
__global__ void conv_x_kernel(const float* __restrict__ x, int total) {
    int i = blockIdx.x * blockDim.x + threadIdx.x;
    if (i >= total) return;
    __nv_bfloat16 h, l;
    split_bf16(x[i], h, l);
    d_Xh[i] = h;
    d_Xl[i] = l;
}

// ---------------- weight packing: Wt[n][k] hi/lo, n in padded layout ----------------
__global__ void pack_kernel(const float* __restrict__ Wsrc, const float* __restrict__ Wlin,
                            const float* __restrict__ Wdst, const float* __restrict__ atts,
                            const float* __restrict__ attd, int K) {
    int n = blockIdx.x;   // 0..575
    int k = threadIdx.x;  // 0..255
    if (k >= K) return;
    float w;
    if (n < 256) {
        w = Wsrc[k * D1 + n];
    } else if (n < 260) {
        int h = n - 256;
        float s = 0.f;
        #pragma unroll 8
        for (int c = 0; c < 64; c++) s += Wsrc[k * D1 + h * 64 + c] * atts[h * 64 + c];
        w = s;
    } else if (n < 264) {
        int h = n - 260;
        float s = 0.f;
        #pragma unroll 8
        for (int c = 0; c < 64; c++) s += Wdst[k * D1 + h * 64 + c] * attd[h * 64 + c];
        w = s;
    } else if (n < N_XS) {
        w = 0.f;
    } else {
        w = Wlin[k * D1 + (n - N_XS)];
    }
    __nv_bfloat16 h, l;
    split_bf16(w, h, l);
    d_Wth[n * KMAX + k] = h;
    d_Wtl[n * KMAX + k] = l;
}

// ---------------- bf16 tensor-core GEMM with 2-term split ----------------
// Y[m][n] = X[m][:] . Wt[n][:], computed as XhWh + XhWl + XlWh.
// BM=128, BN=64, BK=32, 256 threads = 8 warps (2 x 4), warp tile 64x16.
__device__ __forceinline__ void mma16816(float* d, const uint32_t* a, const uint32_t* b) {
    asm volatile(
        "mma.sync.aligned.m16n8k16.row.col.f32.bf16.bf16.f32 "
        "{%0,%1,%2,%3}, {%4,%5,%6,%7}, {%8,%9}, {%0,%1,%2,%3};\n"
        : "+f"(d[0]), "+f"(d[1]), "+f"(d[2]), "+f"(d[3])
        : "r"(a[0]), "r"(a[1]), "r"(a[2]), "r"(a[3]), "r"(b[0]), "r"(b[1]));
}

#define SKA 40  // smem k-stride (bf16) for conflict-free fragment loads

__global__ void __launch_bounds__(256) mma_gemm_kernel(const float* __restrict__ blin, int K) {
    __shared__ __nv_bfloat16 sAh[128][SKA], sAl[128][SKA];
    __shared__ __nv_bfloat16 sBh[64][SKA],  sBl[64][SKA];

    const int t    = threadIdx.x;
    const int warp = t >> 5, lane = t & 31;
    const int wm = warp >> 2, wn = warp & 3;
    const int g = lane >> 2, tig = lane & 3;
    const int bn0 = blockIdx.x * 64, bm0 = blockIdx.y * 128;

    float acc[4][2][4];
    #pragma unroll
    for (int mi = 0; mi < 4; mi++)
        #pragma unroll
        for (int ni = 0; ni < 2; ni++)
            #pragma unroll
            for (int c = 0; c < 4; c++) acc[mi][ni][c] = 0.f;

    for (int k0 = 0; k0 < K; k0 += 32) {
        // ---- load A tile (128 x 32) hi+lo: 4 uint2 per thread per matrix ----
        #pragma unroll
        for (int l = 0; l < 4; l++) {
            int f = t + l * 256;
            int row = f >> 3, kq = (f & 7) * 4;
            int m = bm0 + row;
            uint2 vh = make_uint2(0u, 0u), vl = make_uint2(0u, 0u);
            if (m < N_NODES) {
                vh = *(const uint2*)&d_Xh[(size_t)m * K + k0 + kq];
                vl = *(const uint2*)&d_Xl[(size_t)m * K + k0 + kq];
            }
            *(uint2*)&sAh[row][kq] = vh;
            *(uint2*)&sAl[row][kq] = vl;
        }
        // ---- load B tile (64 x 32) hi+lo: 2 uint2 per thread per matrix ----
        #pragma unroll
        for (int l = 0; l < 2; l++) {
            int f = t + l * 256;
            int row = f >> 3, kq = (f & 7) * 4;
            int n = bn0 + row;
            *(uint2*)&sBh[row][kq] = *(const uint2*)&d_Wth[(size_t)n * KMAX + k0 + kq];
            *(uint2*)&sBl[row][kq] = *(const uint2*)&d_Wtl[(size_t)n * KMAX + k0 + kq];
        }
        __syncthreads();

        #pragma unroll
        for (int ks = 0; ks < 32; ks += 16) {
            // B fragments (hi & lo) for this warp's 2 n8 tiles
            uint32_t bh[2][2], bl[2][2];
            #pragma unroll
            for (int ni = 0; ni < 2; ni++) {
                int nr = wn * 16 + ni * 8 + g;
                bh[ni][0] = *(const uint32_t*)&sBh[nr][ks + 2 * tig];
                bh[ni][1] = *(const uint32_t*)&sBh[nr][ks + 2 * tig + 8];
                bl[ni][0] = *(const uint32_t*)&sBl[nr][ks + 2 * tig];
                bl[ni][1] = *(const uint32_t*)&sBl[nr][ks + 2 * tig + 8];
            }
            #pragma unroll
            for (int mi = 0; mi < 4; mi++) {
                int rb = wm * 64 + mi * 16;
                uint32_t ah[4], al[4];
                ah[0] = *(const uint32_t*)&sAh[rb + g][ks + 2 * tig];
                ah[1] = *(const uint32_t*)&sAh[rb + g + 8][ks + 2 * tig];
                ah[2] = *(const uint32_t*)&sAh[rb + g][ks + 2 * tig + 8];
                ah[3] = *(const uint32_t*)&sAh[rb + g + 8][ks + 2 * tig + 8];
                al[0] = *(const uint32_t*)&sAl[rb + g][ks + 2 * tig];
                al[1] = *(const uint32_t*)&sAl[rb + g + 8][ks + 2 * tig];
                al[2] = *(const uint32_t*)&sAl[rb + g][ks + 2 * tig + 8];
                al[3] = *(const uint32_t*)&sAl[rb + g + 8][ks + 2 * tig + 8];
                #pragma unroll
                for (int ni = 0; ni < 2; ni++) {
                    mma16816(acc[mi][ni], ah, bh[ni]);  // hi*hi
                    mma16816(acc[mi][ni], ah, bl[ni]);  // hi*lo
                    mma16816(acc[mi][ni], al, bh[ni]);  // lo*hi
                }
            }
        }
        __syncthreads();
    }

    // ---- epilogue: route to d_Xs / d_Lin (+blin), float2 stores ----
    #pragma unroll
    for (int mi = 0; mi < 4; mi++) {
        int r0 = bm0 + wm * 64 + mi * 16 + g;
        int r1 = r0 + 8;
        #pragma unroll
        for (int ni = 0; ni < 2; ni++) {
            int n = bn0 + wn * 16 + ni * 8 + 2 * tig;
            float2 v0 = make_float2(acc[mi][ni][0], acc[mi][ni][1]);
            float2 v1 = make_float2(acc[mi][ni][2], acc[mi][ni][3]);
            if (n < N_XS) {
                if (r0 < N_NODES) *(float2*)&d_Xs[(size_t)r0 * N_XS + n] = v0;
                if (r1 < N_NODES) *(float2*)&d_Xs[(size_t)r1 * N_XS + n] = v1;
            } else {
                int nn = n - N_XS;
                float bx = blin[nn], by = blin[nn + 1];
                v0.x += bx; v0.y += by;
                v1.x += bx; v1.y += by;
                if (r0 < N_NODES) *(float2*)&d_Lin[(size_t)r0 * N_LIN + nn] = v0;
                if (r1 < N_NODES) *(float2*)&d_Lin[(size_t)r1 * N_LIN + nn] = v1;
            }
        }
    }
}

// -------- fused softmax + aggregation: one warp per node --------
// do_ln=1: LayerNorm+ReLU epilogue, writes bf16 hi/lo of h into d_Xh/d_Xl (layer-2 GEMM input).
// do_ln=0: plain epilogue to out_param.
__global__ void aggr_kernel(const float* __restrict__ bias,
                            const float* __restrict__ gamma, const float* __restrict__ beta,
                            float* __restrict__ out_param, int do_ln) {
    int wid  = (blockIdx.x * blockDim.x + threadIdx.x) >> 5;
    int lane = threadIdx.x & 31;
    if (wid >= N_NODES) return;
    int node = wid;
    int row0 = d_rowptr[node];
    int deg  = d_rowptr[node + 1] - row0;

    float m0 = -1e30f, m1 = -1e30f, m2 = -1e30f, m3 = -1e30f;
    if (deg > 0) {
        const float4 adv = *(const float4*)&d_Xs[(size_t)node * N_XS + 260];
        for (int i = lane; i < deg; i += 32) {
            int s = d_srcs[row0 + i];
            const float4 as4 = __ldg((const float4*)&d_Xs[(size_t)s * N_XS + 256]);
            float e0 = as4.x + adv.x; e0 = e0 > 0.f ? e0 : 0.2f * e0;
            float e1 = as4.y + adv.y; e1 = e1 > 0.f ? e1 : 0.2f * e1;
            float e2 = as4.z + adv.z; e2 = e2 > 0.f ? e2 : 0.2f * e2;
            float e3 = as4.w + adv.w; e3 = e3 > 0.f ? e3 : 0.2f * e3;
            *(float4*)&d_alpha[(size_t)(row0 + i) * 4] = make_float4(e0, e1, e2, e3);
            m0 = fmaxf(m0, e0); m1 = fmaxf(m1, e1); m2 = fmaxf(m2, e2); m3 = fmaxf(m3, e3);
        }
        #pragma unroll
        for (int off = 16; off; off >>= 1) {
            m0 = fmaxf(m0, __shfl_xor_sync(0xffffffffu, m0, off));
            m1 = fmaxf(m1, __shfl_xor_sync(0xffffffffu, m1, off));
            m2 = fmaxf(m2, __shfl_xor_sync(0xffffffffu, m2, off));
            m3 = fmaxf(m3, __shfl_xor_sync(0xffffffffu, m3, off));
        }
    }

    float s0 = 0.f, s1 = 0.f, s2 = 0.f, s3 = 0.f;
    for (int i = lane; i < deg; i += 32) {
        float4 e = *(const float4*)&d_alpha[(size_t)(row0 + i) * 4];
        s0 += __expf(e.x - m0); s1 += __expf(e.y - m1);
        s2 += __expf(e.z - m2); s3 += __expf(e.w - m3);
    }
    #pragma unroll
    for (int off = 16; off; off >>= 1) {
        s0 += __shfl_xor_sync(0xffffffffu, s0, off);
        s1 += __shfl_xor_sync(0xffffffffu, s1, off);
        s2 += __shfl_xor_sync(0xffffffffu, s2, off);
        s3 += __shfl_xor_sync(0xffffffffu, s3, off);
    }
    float r[4] = {1.f / (s0 + 1e-16f), 1.f / (s1 + 1e-16f),
                  1.f / (s2 + 1e-16f), 1.f / (s3 + 1e-16f)};
    float mh[4] = {m0, m1, m2, m3};

    float acc[8] = {};
    int i = 0;
    for (; i + 2 <= deg; i += 2) {
        int p = row0 + i;
        int sA = d_srcs[p], sB = d_srcs[p + 1];
        float4 eA = *(const float4*)&d_alpha[(size_t)p * 4];
        float4 eB = *(const float4*)&d_alpha[(size_t)(p + 1) * 4];
        const float* xA = &d_Xs[(size_t)sA * N_XS + lane];
        const float* xB = &d_Xs[(size_t)sB * N_XS + lane];
        float vA[8], vB[8];
        #pragma unroll
        for (int j = 0; j < 8; j++) vA[j] = xA[j * 32];
        #pragma unroll
        for (int j = 0; j < 8; j++) vB[j] = xB[j * 32];
        float aA[4] = {__expf(eA.x - mh[0]) * r[0], __expf(eA.y - mh[1]) * r[1],
                       __expf(eA.z - mh[2]) * r[2], __expf(eA.w - mh[3]) * r[3]};
        float aB[4] = {__expf(eB.x - mh[0]) * r[0], __expf(eB.y - mh[1]) * r[1],
                       __expf(eB.z - mh[2]) * r[2], __expf(eB.w - mh[3]) * r[3]};
        #pragma unroll
        for (int j = 0; j < 8; j++) acc[j] += aA[j >> 1] * vA[j] + aB[j >> 1] * vB[j];
    }
    for (; i < deg; i++) {
        int p = row0 + i;
        int s = d_srcs[p];
        float4 e = *(const float4*)&d_alpha[(size_t)p * 4];
        const float* xr = &d_Xs[(size_t)s * N_XS + lane];
        float a[4] = {__expf(e.x - mh[0]) * r[0], __expf(e.y - mh[1]) * r[1],
                      __expf(e.z - mh[2]) * r[2], __expf(e.w - mh[3]) * r[3]};
        #pragma unroll
        for (int j = 0; j < 8; j++) acc[j] += a[j >> 1] * xr[j * 32];
    }

    const float* yrow = &d_Lin[(size_t)node * N_LIN + lane];
    #pragma unroll
    for (int j = 0; j < 8; j++) acc[j] += yrow[j * 32] + bias[lane + j * 32];

    if (do_ln) {
        float sum = 0.f;
        #pragma unroll
        for (int j = 0; j < 8; j++) sum += acc[j];
        #pragma unroll
        for (int off = 16; off; off >>= 1) sum += __shfl_xor_sync(0xffffffffu, sum, off);
        float mu = sum * (1.f / 256.f);
        float vs = 0.f;
        #pragma unroll
        for (int j = 0; j < 8; j++) vs += (acc[j] - mu) * (acc[j] - mu);
        #pragma unroll
        for (int off = 16; off; off >>= 1) vs += __shfl_xor_sync(0xffffffffu, vs, off);
        float rstd = rsqrtf(vs * (1.f / 256.f) + 1e-5f);
        #pragma unroll
        for (int j = 0; j < 8; j++) {
            int c = lane + j * 32;
            float y = (acc[j] - mu) * rstd * gamma[c] + beta[c];
            y = y > 0.f ? y : 0.f;
            __nv_bfloat16 h, l;
            split_bf16(y, h, l);
            d_Xh[(size_t)node * D1 + c] = h;
            d_Xl[(size_t)node * D1 + c] = l;
        }
    } else {
        #pragma unroll
        for (int j = 0; j < 8; j++)
            out_param[(size_t)node * D1 + lane + j * 32] = acc[j];
    }
}

// ---------------- launch ----------------
extern "C" void kernel_launch(void* const* d_in, const int* in_sizes, int n_in,
                              void* d_out, int out_size) {
    const float* x      = (const float*)d_in[0];
    const int*   ei     = (const int*)d_in[1];
    const int*   src    = ei;
    const int*   dst    = ei + N_EDGES;
    const float* Wsrc1  = (const float*)d_in[2];
    const float* Wdst1  = (const float*)d_in[3];
    const float* atts1  = (const float*)d_in[4];
    const float* attd1  = (const float*)d_in[5];
    const float* b1     = (const float*)d_in[6];
    const float* Wlin1  = (const float*)d_in[7];
    const float* blin1  = (const float*)d_in[8];
    const float* gamma  = (const float*)d_in[9];
    const float* beta   = (const float*)d_in[10];
    const float* Wsrc2  = (const float*)d_in[11];
    const float* Wdst2  = (const float*)d_in[12];
    const float* atts2  = (const float*)d_in[13];
    const float* attd2  = (const float*)d_in[14];
    const float* b2     = (const float*)d_in[15];
    const float* Wlin2  = (const float*)d_in[16];
    const float* blin2  = (const float*)d_in[17];
    float* out = (float*)d_out;

    const int scan_blocks = (N_NODES + 511) / 512;  // 98

    // CSR build (per-launch, idempotent)
    zero_deg_kernel<<<(N_NODES + 255) / 256, 256>>>();
    count_deg_kernel<<<(N_EDGES + 255) / 256, 256>>>(dst);
    scan1_kernel<<<scan_blocks, 512>>>();
    scan2_kernel<<<1, 32>>>(scan_blocks);
    scan3_kernel<<<scan_blocks, 512>>>();
    fill_csr_kernel<<<(N_EDGES + 255) / 256, 256>>>(src, dst);

    dim3 ggrid(NCP / 64, (N_NODES + 127) / 128);  // (9, 391)

    // ---- layer 1 ----
    conv_x_kernel<<<(N_NODES * DIN + 255) / 256, 256>>>(x, N_NODES * DIN);
    pack_kernel<<<NCP, 256>>>(Wsrc1, Wlin1, Wdst1, atts1, attd1, DIN);
    mma_gemm_kernel<<<ggrid, 256>>>(blin1, DIN);
    aggr_kernel<<<(N_NODES + 7) / 8, 256>>>(b1, gamma, beta, nullptr, /*do_ln=*/1);

    // ---- layer 2 ----
    pack_kernel<<<NCP, 256>>>(Wsrc2, Wlin2, Wdst2, atts2, attd2, D1);
    mma_gemm_kernel<<<ggrid, 256>>>(blin2, D1);
    aggr_kernel<<<(N_NODES + 7) / 8, 256>>>(b2, nullptr, nullptr, out, /*do_ln=*/0);
}